// round 1
// baseline (speedup 1.0000x reference)
#include <cuda_runtime.h>
#include <math.h>

#define BM 64
#define BN 64
#define DH 128
#define KST 132   // smem row stride (floats) for Q/K/V tiles: conflict-free strided rows
#define PST 68    // smem row stride for P tile
#define NTH 256

// ---- packed f32x2 helpers (sm_103a: doubles FFMA throughput vs scalar FFMA) ----
__device__ __forceinline__ unsigned long long fma2(unsigned long long a,
                                                   unsigned long long b,
                                                   unsigned long long c) {
    unsigned long long d;
    asm("fma.rn.f32x2 %0, %1, %2, %3;" : "=l"(d) : "l"(a), "l"(b), "l"(c));
    return d;
}
__device__ __forceinline__ unsigned long long mul2(unsigned long long a,
                                                   unsigned long long b) {
    unsigned long long d;
    asm("mul.rn.f32x2 %0, %1, %2;" : "=l"(d) : "l"(a), "l"(b));
    return d;
}
__device__ __forceinline__ unsigned long long pack2(float x, float y) {
    unsigned long long r;
    unsigned int xi = __float_as_uint(x), yi = __float_as_uint(y);
    asm("mov.b64 %0, {%1, %2};" : "=l"(r) : "r"(xi), "r"(yi));
    return r;
}
__device__ __forceinline__ float2 unpack2(unsigned long long v) {
    unsigned int lo, hi;
    asm("mov.b64 {%0, %1}, %2;" : "=r"(lo), "=r"(hi) : "l"(v));
    return make_float2(__uint_as_float(lo), __uint_as_float(hi));
}

__global__ __launch_bounds__(NTH, 1)
void fa_fp32x2_kernel(const float* __restrict__ gq, const float* __restrict__ gk,
                      const float* __restrict__ gv, float* __restrict__ gout,
                      int S)
{
    extern __shared__ float sm[];
    float* Qs = sm;                 // [64][132]
    float* Ks = Qs + BM * KST;      // [64][132]
    float* Vs = Ks + BN * KST;      // [64][132]
    float* Ps = Vs + BN * KST;      // [64][68]

    const int qt  = blockIdx.x;     // q tile index
    const int bh  = blockIdx.y;     // fused batch*head
    const int tid = threadIdx.x;
    const int ty  = tid >> 4;       // 0..15 : owns rows ty*4 .. ty*4+3
    const int tx  = tid & 15;       // 0..15 : owns score cols {tx + 16*j}
    const int row0  = ty * 4;
    const int grow0 = qt * BM + row0;

    const float* qb  = gq + ((size_t)bh * S + (size_t)qt * BM) * DH;
    const float* kbh = gk + (size_t)bh * S * DH;
    const float* vbh = gv + (size_t)bh * S * DH;
    float*       ob  = gout + ((size_t)bh * S + (size_t)qt * BM) * DH;

    // Load Q tile (64x128), 8 float4 per thread, coalesced.
    #pragma unroll
    for (int i = 0; i < 8; i++) {
        int f = tid + i * NTH;              // 0..2047 float4 index
        int r = f >> 5, c4 = f & 31;        // 32 float4 per row
        float4 val = ((const float4*)qb)[f];
        *(float4*)&Qs[r * KST + c4 * 4] = val;
    }

    float m_i[4], l_i[4];
    unsigned long long acc2[4][4];          // O accum: 4 rows x 8 cols as 4 f32x2
    #pragma unroll
    for (int i = 0; i < 4; i++) {
        m_i[i] = -INFINITY; l_i[i] = 0.f;
        #pragma unroll
        for (int j = 0; j < 4; j++) acc2[i][j] = 0ull;
    }

    for (int kt = 0; kt <= qt; kt++) {      // causal: only lower-triangular k tiles
        __syncthreads();                    // prev PV done before overwriting Ks/Vs
        const float* kb = kbh + (size_t)kt * BN * DH;
        const float* vb = vbh + (size_t)kt * BN * DH;
        #pragma unroll
        for (int i = 0; i < 8; i++) {
            int f = tid + i * NTH;
            int r = f >> 5, c4 = f & 31;
            float4 kval = ((const float4*)kb)[f];
            float4 vval = ((const float4*)vb)[f];
            *(float4*)&Ks[r * KST + c4 * 4] = kval;
            *(float4*)&Vs[r * KST + c4 * 4] = vval;
        }
        __syncthreads();

        // ---- S = Q K^T, f32x2-packed over d pairs ----
        unsigned long long s2[4][4];
        #pragma unroll
        for (int i = 0; i < 4; i++)
            #pragma unroll
            for (int j = 0; j < 4; j++) s2[i][j] = 0ull;

        #pragma unroll 4
        for (int d4 = 0; d4 < DH / 4; d4++) {
            ulonglong2 qv[4];
            #pragma unroll
            for (int i = 0; i < 4; i++)
                qv[i] = *(const ulonglong2*)&Qs[(row0 + i) * KST + d4 * 4];
            #pragma unroll
            for (int j = 0; j < 4; j++) {
                ulonglong2 kv = *(const ulonglong2*)&Ks[(tx + 16 * j) * KST + d4 * 4];
                #pragma unroll
                for (int i = 0; i < 4; i++) {
                    s2[i][j] = fma2(qv[i].x, kv.x, s2[i][j]);
                    s2[i][j] = fma2(qv[i].y, kv.y, s2[i][j]);
                }
            }
        }

        // ---- online softmax (per row; stats reduced over the 16 tx lanes) ----
        const bool diag = (kt == qt);
        float p[4][4];
        #pragma unroll
        for (int i = 0; i < 4; i++) {
            float mnew = m_i[i];
            #pragma unroll
            for (int j = 0; j < 4; j++) {
                float2 u = unpack2(s2[i][j]);
                float sv = u.x + u.y;
                if (diag && (kt * BN + tx + 16 * j > grow0 + i)) sv = -INFINITY;
                p[i][j] = sv;
                mnew = fmaxf(mnew, sv);
            }
            #pragma unroll
            for (int off = 8; off; off >>= 1)
                mnew = fmaxf(mnew, __shfl_xor_sync(0xffffffffu, mnew, off));
            float alpha = __expf(m_i[i] - mnew);   // 0 on first block (m_i = -inf)
            m_i[i] = mnew;
            float rs = 0.f;
            #pragma unroll
            for (int j = 0; j < 4; j++) {
                float e = __expf(p[i][j] - mnew);  // exp(-inf)=0 for masked
                p[i][j] = e;
                rs += e;
            }
            #pragma unroll
            for (int off = 8; off; off >>= 1)
                rs += __shfl_xor_sync(0xffffffffu, rs, off);
            l_i[i] = l_i[i] * alpha + rs;
            unsigned long long av = pack2(alpha, alpha);
            #pragma unroll
            for (int j = 0; j < 4; j++)
                acc2[i][j] = mul2(acc2[i][j], av);
            #pragma unroll
            for (int j = 0; j < 4; j++)
                Ps[(row0 + i) * PST + tx + 16 * j] = p[i][j];
        }
        __syncthreads();                    // Ps visible to all before PV

        // ---- O += P V, f32x2-packed over output-column pairs ----
        #pragma unroll 2
        for (int kk = 0; kk < BN; kk++) {
            unsigned long long pp[4];
            #pragma unroll
            for (int i = 0; i < 4; i++) {
                float pv = Ps[(row0 + i) * PST + kk];
                pp[i] = pack2(pv, pv);
            }
            ulonglong2 va  = *(const ulonglong2*)&Vs[kk * KST + tx * 8];
            ulonglong2 vb2 = *(const ulonglong2*)&Vs[kk * KST + tx * 8 + 4];
            #pragma unroll
            for (int i = 0; i < 4; i++) {
                acc2[i][0] = fma2(pp[i], va.x,  acc2[i][0]);
                acc2[i][1] = fma2(pp[i], va.y,  acc2[i][1]);
                acc2[i][2] = fma2(pp[i], vb2.x, acc2[i][2]);
                acc2[i][3] = fma2(pp[i], vb2.y, acc2[i][3]);
            }
        }
    }

    // ---- finalize: O /= l, store coalesced float4 ----
    #pragma unroll
    for (int i = 0; i < 4; i++) {
        float inv = 1.0f / l_i[i];
        float2 a0 = unpack2(acc2[i][0]);
        float2 a1 = unpack2(acc2[i][1]);
        float2 a2 = unpack2(acc2[i][2]);
        float2 a3 = unpack2(acc2[i][3]);
        float4 o0 = make_float4(a0.x * inv, a0.y * inv, a1.x * inv, a1.y * inv);
        float4 o1 = make_float4(a2.x * inv, a2.y * inv, a3.x * inv, a3.y * inv);
        *(float4*)&ob[(row0 + i) * DH + tx * 8]     = o0;
        *(float4*)&ob[(row0 + i) * DH + tx * 8 + 4] = o1;
    }
}

extern "C" void kernel_launch(void* const* d_in, const int* in_sizes, int n_in,
                              void* d_out, int out_size) {
    const float* q = (const float*)d_in[0];
    const float* k = (const float*)d_in[1];
    const float* v = (const float*)d_in[2];
    // d_in[3] is the causal mask (tril) — semantics implemented directly.
    float* out = (float*)d_out;
    const int S = 2048, D = 128;
    const int BH = in_sizes[0] / (S * D);   // 32
    size_t smem = (size_t)(3 * BM * KST + BM * PST) * sizeof(float);  // 118784 B
    cudaFuncSetAttribute(fa_fp32x2_kernel,
                         cudaFuncAttributeMaxDynamicSharedMemorySize, (int)smem);
    dim3 grid(S / BM, BH);
    fa_fp32x2_kernel<<<grid, NTH, smem>>>(q, k, v, out, S);
}

// round 2
// speedup vs baseline: 1.0047x; 1.0047x over previous
#include <cuda_runtime.h>
#include <math.h>

#define BM 64
#define BN 64
#define DH 128
#define KST 132   // smem row stride (floats) for Q/K/V tiles: conflict-free strided rows
#define PST 68    // smem row stride for P tile
#define NTH 256

// ---- packed f32x2 helpers (sm_103a: doubles FFMA throughput vs scalar FFMA) ----
__device__ __forceinline__ unsigned long long fma2(unsigned long long a,
                                                   unsigned long long b,
                                                   unsigned long long c) {
    unsigned long long d;
    asm("fma.rn.f32x2 %0, %1, %2, %3;" : "=l"(d) : "l"(a), "l"(b), "l"(c));
    return d;
}
__device__ __forceinline__ unsigned long long mul2(unsigned long long a,
                                                   unsigned long long b) {
    unsigned long long d;
    asm("mul.rn.f32x2 %0, %1, %2;" : "=l"(d) : "l"(a), "l"(b));
    return d;
}
__device__ __forceinline__ unsigned long long pack2(float x, float y) {
    unsigned long long r;
    unsigned int xi = __float_as_uint(x), yi = __float_as_uint(y);
    asm("mov.b64 %0, {%1, %2};" : "=l"(r) : "r"(xi), "r"(yi));
    return r;
}
__device__ __forceinline__ float2 unpack2(unsigned long long v) {
    unsigned int lo, hi;
    asm("mov.b64 {%0, %1}, %2;" : "=r"(lo), "=r"(hi) : "l"(v));
    return make_float2(__uint_as_float(lo), __uint_as_float(hi));
}

__global__ __launch_bounds__(NTH, 1)
void fa_fp32x2_kernel(const float* __restrict__ gq, const float* __restrict__ gk,
                      const float* __restrict__ gv, float* __restrict__ gout,
                      int S)
{
    extern __shared__ float sm[];
    float* Qs = sm;                 // [64][132]
    float* Ks = Qs + BM * KST;      // [64][132]
    float* Vs = Ks + BN * KST;      // [64][132]
    float* Ps = Vs + BN * KST;      // [64][68]

    const int qt  = blockIdx.x;     // q tile index
    const int bh  = blockIdx.y;     // fused batch*head
    const int tid = threadIdx.x;
    const int ty  = tid >> 4;       // 0..15 : owns rows ty*4 .. ty*4+3
    const int tx  = tid & 15;       // 0..15 : owns score cols {tx + 16*j}
    const int row0  = ty * 4;
    const int grow0 = qt * BM + row0;

    const float* qb  = gq + ((size_t)bh * S + (size_t)qt * BM) * DH;
    const float* kbh = gk + (size_t)bh * S * DH;
    const float* vbh = gv + (size_t)bh * S * DH;
    float*       ob  = gout + ((size_t)bh * S + (size_t)qt * BM) * DH;

    // Load Q tile (64x128), 8 float4 per thread, coalesced.
    #pragma unroll
    for (int i = 0; i < 8; i++) {
        int f = tid + i * NTH;              // 0..2047 float4 index
        int r = f >> 5, c4 = f & 31;        // 32 float4 per row
        float4 val = ((const float4*)qb)[f];
        *(float4*)&Qs[r * KST + c4 * 4] = val;
    }

    float m_i[4], l_i[4];
    unsigned long long acc2[4][4];          // O accum: 4 rows x 8 cols as 4 f32x2
    #pragma unroll
    for (int i = 0; i < 4; i++) {
        m_i[i] = -INFINITY; l_i[i] = 0.f;
        #pragma unroll
        for (int j = 0; j < 4; j++) acc2[i][j] = 0ull;
    }

    for (int kt = 0; kt <= qt; kt++) {      // causal: only lower-triangular k tiles
        __syncthreads();                    // prev PV done before overwriting Ks/Vs
        const float* kb = kbh + (size_t)kt * BN * DH;
        const float* vb = vbh + (size_t)kt * BN * DH;
        #pragma unroll
        for (int i = 0; i < 8; i++) {
            int f = tid + i * NTH;
            int r = f >> 5, c4 = f & 31;
            float4 kval = ((const float4*)kb)[f];
            float4 vval = ((const float4*)vb)[f];
            *(float4*)&Ks[r * KST + c4 * 4] = kval;
            *(float4*)&Vs[r * KST + c4 * 4] = vval;
        }
        __syncthreads();

        // ---- S = Q K^T, f32x2-packed over d pairs ----
        unsigned long long s2[4][4];
        #pragma unroll
        for (int i = 0; i < 4; i++)
            #pragma unroll
            for (int j = 0; j < 4; j++) s2[i][j] = 0ull;

        #pragma unroll 4
        for (int d4 = 0; d4 < DH / 4; d4++) {
            ulonglong2 qv[4];
            #pragma unroll
            for (int i = 0; i < 4; i++)
                qv[i] = *(const ulonglong2*)&Qs[(row0 + i) * KST + d4 * 4];
            #pragma unroll
            for (int j = 0; j < 4; j++) {
                ulonglong2 kv = *(const ulonglong2*)&Ks[(tx + 16 * j) * KST + d4 * 4];
                #pragma unroll
                for (int i = 0; i < 4; i++) {
                    s2[i][j] = fma2(qv[i].x, kv.x, s2[i][j]);
                    s2[i][j] = fma2(qv[i].y, kv.y, s2[i][j]);
                }
            }
        }

        // ---- online softmax (per row; stats reduced over the 16 tx lanes) ----
        const bool diag = (kt == qt);
        float p[4][4];
        #pragma unroll
        for (int i = 0; i < 4; i++) {
            float mnew = m_i[i];
            #pragma unroll
            for (int j = 0; j < 4; j++) {
                float2 u = unpack2(s2[i][j]);
                float sv = u.x + u.y;
                if (diag && (kt * BN + tx + 16 * j > grow0 + i)) sv = -INFINITY;
                p[i][j] = sv;
                mnew = fmaxf(mnew, sv);
            }
            #pragma unroll
            for (int off = 8; off; off >>= 1)
                mnew = fmaxf(mnew, __shfl_xor_sync(0xffffffffu, mnew, off));
            float alpha = __expf(m_i[i] - mnew);   // 0 on first block (m_i = -inf)
            m_i[i] = mnew;
            float rs = 0.f;
            #pragma unroll
            for (int j = 0; j < 4; j++) {
                float e = __expf(p[i][j] - mnew);  // exp(-inf)=0 for masked
                p[i][j] = e;
                rs += e;
            }
            #pragma unroll
            for (int off = 8; off; off >>= 1)
                rs += __shfl_xor_sync(0xffffffffu, rs, off);
            l_i[i] = l_i[i] * alpha + rs;
            unsigned long long av = pack2(alpha, alpha);
            #pragma unroll
            for (int j = 0; j < 4; j++)
                acc2[i][j] = mul2(acc2[i][j], av);
            #pragma unroll
            for (int j = 0; j < 4; j++)
                Ps[(row0 + i) * PST + tx + 16 * j] = p[i][j];
        }
        __syncthreads();                    // Ps visible to all before PV

        // ---- O += P V, f32x2-packed over output-column pairs ----
        #pragma unroll 2
        for (int kk = 0; kk < BN; kk++) {
            unsigned long long pp[4];
            #pragma unroll
            for (int i = 0; i < 4; i++) {
                float pv = Ps[(row0 + i) * PST + kk];
                pp[i] = pack2(pv, pv);
            }
            ulonglong2 va  = *(const ulonglong2*)&Vs[kk * KST + tx * 8];
            ulonglong2 vb2 = *(const ulonglong2*)&Vs[kk * KST + tx * 8 + 4];
            #pragma unroll
            for (int i = 0; i < 4; i++) {
                acc2[i][0] = fma2(pp[i], va.x,  acc2[i][0]);
                acc2[i][1] = fma2(pp[i], va.y,  acc2[i][1]);
                acc2[i][2] = fma2(pp[i], vb2.x, acc2[i][2]);
                acc2[i][3] = fma2(pp[i], vb2.y, acc2[i][3]);
            }
        }
    }

    // ---- finalize: O /= l, store coalesced float4 ----
    #pragma unroll
    for (int i = 0; i < 4; i++) {
        float inv = 1.0f / l_i[i];
        float2 a0 = unpack2(acc2[i][0]);
        float2 a1 = unpack2(acc2[i][1]);
        float2 a2 = unpack2(acc2[i][2]);
        float2 a3 = unpack2(acc2[i][3]);
        float4 o0 = make_float4(a0.x * inv, a0.y * inv, a1.x * inv, a1.y * inv);
        float4 o1 = make_float4(a2.x * inv, a2.y * inv, a3.x * inv, a3.y * inv);
        *(float4*)&ob[(row0 + i) * DH + tx * 8]     = o0;
        *(float4*)&ob[(row0 + i) * DH + tx * 8 + 4] = o1;
    }
}

extern "C" void kernel_launch(void* const* d_in, const int* in_sizes, int n_in,
                              void* d_out, int out_size) {
    const float* q = (const float*)d_in[0];
    const float* k = (const float*)d_in[1];
    const float* v = (const float*)d_in[2];
    // d_in[3] is the causal mask (tril) — semantics implemented directly.
    float* out = (float*)d_out;
    const int S = 2048, D = 128;
    const int BH = in_sizes[0] / (S * D);   // 32
    size_t smem = (size_t)(3 * BM * KST + BM * PST) * sizeof(float);  // 118784 B
    cudaFuncSetAttribute(fa_fp32x2_kernel,
                         cudaFuncAttributeMaxDynamicSharedMemorySize, (int)smem);
    dim3 grid(S / BM, BH);
    fa_fp32x2_kernel<<<grid, NTH, smem>>>(q, k, v, out, S);
}

// round 5
// speedup vs baseline: 3.1225x; 3.1079x over previous
#include <cuda_runtime.h>
#include <math.h>
#include <stdint.h>

#define NTH 256
#define BM 128
#define BN 64

// smem byte offsets: bf16 tiles, 256B per row (128 bf16), XOR-swizzled 16B granules
#define SM_QHI 0
#define SM_QLO 32768
#define SM_KHI 65536
#define SM_KLO 81920
#define SM_VHI 98304
#define SM_VLO 114688
#define SM_TOTAL 131072

static __device__ __forceinline__ uint32_t s2u(const void* p) {
    return (uint32_t)__cvta_generic_to_shared((void*)p);
}

// split fp32 pair -> bf16x2 hi + bf16x2 lo (rn split; lo compensates hi)
static __device__ __forceinline__ void split2(float x, float y,
                                              uint32_t& hi, uint32_t& lo) {
    uint32_t h2;
    asm("cvt.rn.bf16x2.f32 %0, %1, %2;" : "=r"(h2) : "f"(y), "f"(x));
    float hx = __uint_as_float(h2 << 16);
    float hy = __uint_as_float(h2 & 0xffff0000u);
    float lx = x - hx, ly = y - hy;
    uint32_t l2;
    asm("cvt.rn.bf16x2.f32 %0, %1, %2;" : "=r"(l2) : "f"(ly), "f"(lx));
    hi = h2; lo = l2;
}

static __device__ __forceinline__ void ldsm4(uint32_t* r, uint32_t a) {
    asm volatile("ldmatrix.sync.aligned.m8n8.x4.shared.b16 {%0,%1,%2,%3}, [%4];"
                 : "=r"(r[0]), "=r"(r[1]), "=r"(r[2]), "=r"(r[3]) : "r"(a));
}
static __device__ __forceinline__ void ldsm4t(uint32_t* r, uint32_t a) {
    asm volatile("ldmatrix.sync.aligned.m8n8.x4.trans.shared.b16 {%0,%1,%2,%3}, [%4];"
                 : "=r"(r[0]), "=r"(r[1]), "=r"(r[2]), "=r"(r[3]) : "r"(a));
}

static __device__ __forceinline__ void mma16816(float* c, const uint32_t* a,
                                                uint32_t b0, uint32_t b1) {
    asm volatile(
        "mma.sync.aligned.m16n8k16.row.col.f32.bf16.bf16.f32 "
        "{%0,%1,%2,%3}, {%4,%5,%6,%7}, {%8,%9}, {%0,%1,%2,%3};"
        : "+f"(c[0]), "+f"(c[1]), "+f"(c[2]), "+f"(c[3])
        : "r"(a[0]), "r"(a[1]), "r"(a[2]), "r"(a[3]), "r"(b0), "r"(b1));
}

// swizzled byte offset for (row, 16B-granule g, 8B half hb) in a 256B-row tile
static __device__ __forceinline__ uint32_t swz(int row, int g, int hb) {
    return (uint32_t)row * 256u + (uint32_t)((g ^ (row & 7)) << 4) + (uint32_t)hb * 8u;
}

__global__ __launch_bounds__(NTH, 1)
void fa_mma_kernel(const float* __restrict__ gq, const float* __restrict__ gk,
                   const float* __restrict__ gv, float* __restrict__ go)
{
    extern __shared__ char smem[];
    const uint32_t sb = s2u(smem);
    const int tid = threadIdx.x;
    const int w   = tid >> 5, ln = tid & 31;
    const int grp = ln >> 2, tg = ln & 3;
    const int l15 = ln & 15, l16 = ln >> 4;
    const int qt  = blockIdx.x, bh = blockIdx.y;
    const int S   = 2048;

    const float* qb  = gq + ((size_t)bh * S + (size_t)qt * BM) * 128;
    const float* kbh = gk + (size_t)bh * S * 128;
    const float* vbh = gv + (size_t)bh * S * 128;
    float*       ob  = go + ((size_t)bh * S + (size_t)qt * BM) * 128;

    // ---- Q: load fp32, split to bf16 hi/lo in smem (once) ----
    #pragma unroll
    for (int i = 0; i < 16; i++) {
        int f = tid + i * NTH;               // float4 idx; row=f>>5, c4=f&31
        int r = f >> 5, c4 = f & 31;
        float4 qq = ((const float4*)qb)[f];
        uint32_t h0, l0, h1, l1;
        split2(qq.x, qq.y, h0, l0);
        split2(qq.z, qq.w, h1, l1);
        uint32_t off = swz(r, c4 >> 1, c4 & 1);
        *(uint2*)(smem + SM_QHI + off) = make_uint2(h0, h1);
        *(uint2*)(smem + SM_QLO + off) = make_uint2(l0, l1);
    }

    float o_[16][4];
    #pragma unroll
    for (int j = 0; j < 16; j++)
        #pragma unroll
        for (int e = 0; e < 4; e++) o_[j][e] = 0.f;
    float mA = -INFINITY, mB = -INFINITY, lA = 0.f, lB = 0.f;

    const int qr = w * 16 + l15;             // ldmatrix source row for Q frags
    const uint32_t qbaseH = sb + SM_QHI + qr * 256;
    const uint32_t qbaseL = sb + SM_QLO + qr * 256;
    const int qx = qr & 7;

    const int grow0 = qt * 128 + w * 16 + grp;   // global q-row of c0/c1
    const int nch = 2 * qt + 2;

    for (int c = 0; c < nch; c++) {
        __syncthreads();                     // prior chunk's ldmatrix reads done
        const float* kb = kbh + (size_t)c * BN * 128;
        const float* vb = vbh + (size_t)c * BN * 128;
        #pragma unroll
        for (int i = 0; i < 8; i++) {
            int f = tid + i * NTH;           // rows 0..63
            int r = f >> 5, c4 = f & 31;
            uint32_t off = swz(r, c4 >> 1, c4 & 1);
            float4 kk = ((const float4*)kb)[f];
            uint32_t h0, l0, h1, l1;
            split2(kk.x, kk.y, h0, l0);
            split2(kk.z, kk.w, h1, l1);
            *(uint2*)(smem + SM_KHI + off) = make_uint2(h0, h1);
            *(uint2*)(smem + SM_KLO + off) = make_uint2(l0, l1);
            float4 vv = ((const float4*)vb)[f];
            split2(vv.x, vv.y, h0, l0);
            split2(vv.z, vv.w, h1, l1);
            *(uint2*)(smem + SM_VHI + off) = make_uint2(h0, h1);
            *(uint2*)(smem + SM_VLO + off) = make_uint2(l0, l1);
        }
        __syncthreads();

        // warp-level skip: this warp's rows all above the chunk? (fully masked)
        if (c * 64 > qt * 128 + w * 16 + 15) continue;

        // ---- S = Q K^T  (3-way split: hi*hi + lo*hi + hi*lo) ----
        float sc[8][4];
        #pragma unroll
        for (int j = 0; j < 8; j++)
            #pragma unroll
            for (int e = 0; e < 4; e++) sc[j][e] = 0.f;

        #pragma unroll
        for (int kb8 = 0; kb8 < 8; kb8++) {
            uint32_t goff = (uint32_t)(((kb8 * 2 + l16) ^ qx) << 4);
            uint32_t qh[4], ql[4];
            ldsm4(qh, qbaseH + goff);
            ldsm4(ql, qbaseL + goff);
            #pragma unroll
            for (int ntp = 0; ntp < 4; ntp++) {
                int kr = ntp * 16 + l15;
                uint32_t koff = swz(kr, kb8 * 2 + l16, 0);
                uint32_t kh[4], kl[4];
                ldsm4(kh, sb + SM_KHI + koff);
                ldsm4(kl, sb + SM_KLO + koff);
                mma16816(sc[2 * ntp],     qh, kh[0], kh[2]);
                mma16816(sc[2 * ntp],     ql, kh[0], kh[2]);
                mma16816(sc[2 * ntp],     qh, kl[0], kl[2]);
                mma16816(sc[2 * ntp + 1], qh, kh[1], kh[3]);
                mma16816(sc[2 * ntp + 1], ql, kh[1], kh[3]);
                mma16816(sc[2 * ntp + 1], qh, kl[1], kl[3]);
            }
        }

        // ---- causal mask (only near the diagonal) ----
        if (c * 64 + 63 > grow0) {
            #pragma unroll
            for (int j = 0; j < 8; j++) {
                int gcol = c * 64 + j * 8 + tg * 2;
                if (gcol     > grow0)     sc[j][0] = -INFINITY;
                if (gcol + 1 > grow0)     sc[j][1] = -INFINITY;
                if (gcol     > grow0 + 8) sc[j][2] = -INFINITY;
                if (gcol + 1 > grow0 + 8) sc[j][3] = -INFINITY;
            }
        }

        // ---- online softmax (warp-local; rows grp and grp+8) ----
        float mx0 = -INFINITY, mx1 = -INFINITY;
        #pragma unroll
        for (int j = 0; j < 8; j++) {
            mx0 = fmaxf(mx0, fmaxf(sc[j][0], sc[j][1]));
            mx1 = fmaxf(mx1, fmaxf(sc[j][2], sc[j][3]));
        }
        mx0 = fmaxf(mx0, __shfl_xor_sync(0xffffffffu, mx0, 1));
        mx0 = fmaxf(mx0, __shfl_xor_sync(0xffffffffu, mx0, 2));
        mx1 = fmaxf(mx1, __shfl_xor_sync(0xffffffffu, mx1, 1));
        mx1 = fmaxf(mx1, __shfl_xor_sync(0xffffffffu, mx1, 2));
        float mn0 = fmaxf(mA, mx0), mn1 = fmaxf(mB, mx1);
        float al0 = __expf(mA - mn0), al1 = __expf(mB - mn1);
        mA = mn0; mB = mn1;
        float s0 = 0.f, s1 = 0.f;
        #pragma unroll
        for (int j = 0; j < 8; j++) {
            sc[j][0] = __expf(sc[j][0] - mn0); s0 += sc[j][0];
            sc[j][1] = __expf(sc[j][1] - mn0); s0 += sc[j][1];
            sc[j][2] = __expf(sc[j][2] - mn1); s1 += sc[j][2];
            sc[j][3] = __expf(sc[j][3] - mn1); s1 += sc[j][3];
        }
        s0 += __shfl_xor_sync(0xffffffffu, s0, 1);
        s0 += __shfl_xor_sync(0xffffffffu, s0, 2);
        s1 += __shfl_xor_sync(0xffffffffu, s1, 1);
        s1 += __shfl_xor_sync(0xffffffffu, s1, 2);
        lA = lA * al0 + s0;
        lB = lB * al1 + s1;
        #pragma unroll
        for (int j = 0; j < 16; j++) {
            o_[j][0] *= al0; o_[j][1] *= al0;
            o_[j][2] *= al1; o_[j][3] *= al1;
        }

        // ---- O += P V  (P from C-frags, split; V via ldmatrix.trans) ----
        #pragma unroll
        for (int s = 0; s < 4; s++) {
            uint32_t ph[4], pl[4];
            split2(sc[2 * s][0],     sc[2 * s][1],     ph[0], pl[0]);
            split2(sc[2 * s][2],     sc[2 * s][3],     ph[1], pl[1]);
            split2(sc[2 * s + 1][0], sc[2 * s + 1][1], ph[2], pl[2]);
            split2(sc[2 * s + 1][2], sc[2 * s + 1][3], ph[3], pl[3]);
            int vr = s * 16 + l15;
            #pragma unroll
            for (int dp = 0; dp < 8; dp++) {
                uint32_t voff = swz(vr, dp * 2 + l16, 0);
                uint32_t vh[4], vl[4];
                ldsm4t(vh, sb + SM_VHI + voff);
                ldsm4t(vl, sb + SM_VLO + voff);
                mma16816(o_[2 * dp],     ph, vh[0], vh[1]);
                mma16816(o_[2 * dp],     pl, vh[0], vh[1]);
                mma16816(o_[2 * dp],     ph, vl[0], vl[1]);
                mma16816(o_[2 * dp + 1], ph, vh[2], vh[3]);
                mma16816(o_[2 * dp + 1], pl, vh[2], vh[3]);
                mma16816(o_[2 * dp + 1], ph, vl[2], vl[3]);
            }
        }
    }

    // ---- epilogue: normalize + store ----
    float inv0 = 1.0f / lA, inv1 = 1.0f / lB;
    float* r0 = ob + (size_t)(w * 16 + grp) * 128 + tg * 2;
    float* r1 = ob + (size_t)(w * 16 + grp + 8) * 128 + tg * 2;
    #pragma unroll
    for (int j = 0; j < 16; j++) {
        *(float2*)(r0 + j * 8) = make_float2(o_[j][0] * inv0, o_[j][1] * inv0);
        *(float2*)(r1 + j * 8) = make_float2(o_[j][2] * inv1, o_[j][3] * inv1);
    }
}

extern "C" void kernel_launch(void* const* d_in, const int* in_sizes, int n_in,
                              void* d_out, int out_size) {
    const float* q = (const float*)d_in[0];
    const float* k = (const float*)d_in[1];
    const float* v = (const float*)d_in[2];
    // d_in[3]: causal tril mask — semantics implemented directly.
    float* out = (float*)d_out;
    const int S = 2048, D = 128;
    const int BH = in_sizes[0] / (S * D);   // 32
    cudaFuncSetAttribute(fa_mma_kernel,
                         cudaFuncAttributeMaxDynamicSharedMemorySize, SM_TOTAL);
    dim3 grid(S / BM, BH);
    fa_mma_kernel<<<grid, NTH, SM_TOTAL>>>(q, k, v, out);
}

// round 6
// speedup vs baseline: 3.1619x; 1.0126x over previous
#include <cuda_runtime.h>
#include <math.h>
#include <stdint.h>

#define NTH 256
#define BM 128
#define BN 64

// smem byte offsets
#define SM_QHI 0
#define SM_QLO 32768
#define SM_KHI 65536
#define SM_KLO 81920
#define SM_VHI 98304
#define SM_VLO 114688
#define SM_STG 131072              // fp32 staging: K 32KB then V 32KB
#define SM_TOTAL (SM_STG + 65536)  // 196608

static __device__ __forceinline__ uint32_t s2u(const void* p) {
    return (uint32_t)__cvta_generic_to_shared((void*)p);
}

// split fp32 pair -> bf16x2 hi + bf16x2 lo (rn split; lo compensates hi)
static __device__ __forceinline__ void split2(float x, float y,
                                              uint32_t& hi, uint32_t& lo) {
    uint32_t h2;
    asm("cvt.rn.bf16x2.f32 %0, %1, %2;" : "=r"(h2) : "f"(y), "f"(x));
    float hx = __uint_as_float(h2 << 16);
    float hy = __uint_as_float(h2 & 0xffff0000u);
    float lx = x - hx, ly = y - hy;
    uint32_t l2;
    asm("cvt.rn.bf16x2.f32 %0, %1, %2;" : "=r"(l2) : "f"(ly), "f"(lx));
    hi = h2; lo = l2;
}

static __device__ __forceinline__ void ldsm4(uint32_t* r, uint32_t a) {
    asm volatile("ldmatrix.sync.aligned.m8n8.x4.shared.b16 {%0,%1,%2,%3}, [%4];"
                 : "=r"(r[0]), "=r"(r[1]), "=r"(r[2]), "=r"(r[3]) : "r"(a));
}
static __device__ __forceinline__ void ldsm4t(uint32_t* r, uint32_t a) {
    asm volatile("ldmatrix.sync.aligned.m8n8.x4.trans.shared.b16 {%0,%1,%2,%3}, [%4];"
                 : "=r"(r[0]), "=r"(r[1]), "=r"(r[2]), "=r"(r[3]) : "r"(a));
}

static __device__ __forceinline__ void mma16816(float* c, const uint32_t* a,
                                                uint32_t b0, uint32_t b1) {
    asm volatile(
        "mma.sync.aligned.m16n8k16.row.col.f32.bf16.bf16.f32 "
        "{%0,%1,%2,%3}, {%4,%5,%6,%7}, {%8,%9}, {%0,%1,%2,%3};"
        : "+f"(c[0]), "+f"(c[1]), "+f"(c[2]), "+f"(c[3])
        : "r"(a[0]), "r"(a[1]), "r"(a[2]), "r"(a[3]), "r"(b0), "r"(b1));
}

static __device__ __forceinline__ void cp16(uint32_t smem_dst, const void* gsrc) {
    asm volatile("cp.async.cg.shared.global [%0], [%1], 16;"
                 :: "r"(smem_dst), "l"(gsrc) : "memory");
}
static __device__ __forceinline__ void cp_commit() {
    asm volatile("cp.async.commit_group;" ::: "memory");
}
static __device__ __forceinline__ void cp_wait0() {
    asm volatile("cp.async.wait_group 0;" ::: "memory");
}

// swizzled byte offset for (row, 16B-granule g, 8B half hb) in a 256B-row tile
static __device__ __forceinline__ uint32_t swz(int row, int g, int hb) {
    return (uint32_t)row * 256u + (uint32_t)((g ^ (row & 7)) << 4) + (uint32_t)hb * 8u;
}

__global__ __launch_bounds__(NTH, 1)
void fa_mma_kernel(const float* __restrict__ gq, const float* __restrict__ gk,
                   const float* __restrict__ gv, float* __restrict__ go)
{
    extern __shared__ char smem[];
    const uint32_t sb = s2u(smem);
    const int tid = threadIdx.x;
    const int w   = tid >> 5, ln = tid & 31;
    const int grp = ln >> 2, tg = ln & 3;
    const int l15 = ln & 15, l16 = ln >> 4;
    const int qt  = (int)gridDim.x - 1 - (int)blockIdx.x;   // heavy CTAs first
    const int bh  = blockIdx.y;
    const int S   = 2048;

    const float* qb  = gq + ((size_t)bh * S + (size_t)qt * BM) * 128;
    const float* kbh = gk + (size_t)bh * S * 128;
    const float* vbh = gv + (size_t)bh * S * 128;
    float*       ob  = go + ((size_t)bh * S + (size_t)qt * BM) * 128;

    // ---- Q: load fp32, split to bf16 hi/lo in smem (once) ----
    #pragma unroll
    for (int i = 0; i < 16; i++) {
        int f = tid + i * NTH;               // float4 idx; row=f>>5, c4=f&31
        int r = f >> 5, c4 = f & 31;
        float4 qq = ((const float4*)qb)[f];
        uint32_t h0, l0, h1, l1;
        split2(qq.x, qq.y, h0, l0);
        split2(qq.z, qq.w, h1, l1);
        uint32_t off = swz(r, c4 >> 1, c4 & 1);
        *(uint2*)(smem + SM_QHI + off) = make_uint2(h0, h1);
        *(uint2*)(smem + SM_QLO + off) = make_uint2(l0, l1);
    }

    // ---- prefetch chunk 0 into fp32 staging via cp.async ----
    {
        const float* kb = kbh;
        const float* vb = vbh;
        #pragma unroll
        for (int i = 0; i < 8; i++) {
            int f = tid + i * NTH;
            cp16(sb + SM_STG         + (uint32_t)f * 16u, (const float4*)kb + f);
            cp16(sb + SM_STG + 32768 + (uint32_t)f * 16u, (const float4*)vb + f);
        }
        cp_commit();
    }

    float o_[16][4];
    #pragma unroll
    for (int j = 0; j < 16; j++)
        #pragma unroll
        for (int e = 0; e < 4; e++) o_[j][e] = 0.f;
    float mA = -INFINITY, mB = -INFINITY, lA = 0.f, lB = 0.f;

    const int qr = w * 16 + l15;             // ldmatrix source row for Q frags
    const uint32_t qbaseH = sb + SM_QHI + qr * 256;
    const uint32_t qbaseL = sb + SM_QLO + qr * 256;
    const int qx = qr & 7;

    const int grow0 = qt * 128 + w * 16 + grp;   // global q-row of c0/c1
    const int nch = 2 * qt + 2;

    for (int c = 0; c < nch; c++) {
        cp_wait0();                          // staging holds chunk c
        __syncthreads();                     // + all warps done reading bf16 bufs

        // ---- convert staging fp32 -> bf16 hi/lo tiles ----
        #pragma unroll
        for (int i = 0; i < 8; i++) {
            int f = tid + i * NTH;           // rows 0..63
            int r = f >> 5, c4 = f & 31;
            uint32_t off = swz(r, c4 >> 1, c4 & 1);
            float4 kk = *(const float4*)(smem + SM_STG + (size_t)f * 16);
            uint32_t h0, l0, h1, l1;
            split2(kk.x, kk.y, h0, l0);
            split2(kk.z, kk.w, h1, l1);
            *(uint2*)(smem + SM_KHI + off) = make_uint2(h0, h1);
            *(uint2*)(smem + SM_KLO + off) = make_uint2(l0, l1);
            float4 vv = *(const float4*)(smem + SM_STG + 32768 + (size_t)f * 16);
            split2(vv.x, vv.y, h0, l0);
            split2(vv.z, vv.w, h1, l1);
            *(uint2*)(smem + SM_VHI + off) = make_uint2(h0, h1);
            *(uint2*)(smem + SM_VLO + off) = make_uint2(l0, l1);
        }
        __syncthreads();                     // bf16 ready; staging reads done

        // ---- kick cp.async for chunk c+1 (overlaps with compute below) ----
        if (c + 1 < nch) {
            const float* kb = kbh + (size_t)(c + 1) * BN * 128;
            const float* vb = vbh + (size_t)(c + 1) * BN * 128;
            #pragma unroll
            for (int i = 0; i < 8; i++) {
                int f = tid + i * NTH;
                cp16(sb + SM_STG         + (uint32_t)f * 16u, (const float4*)kb + f);
                cp16(sb + SM_STG + 32768 + (uint32_t)f * 16u, (const float4*)vb + f);
            }
            cp_commit();
        }

        // warp-level skip: this warp's rows all above the chunk? (fully masked)
        if (c * 64 > qt * 128 + w * 16 + 15) continue;

        // ---- S = Q K^T  (3-way split: hi*hi + lo*hi + hi*lo) ----
        float sc[8][4];
        #pragma unroll
        for (int j = 0; j < 8; j++)
            #pragma unroll
            for (int e = 0; e < 4; e++) sc[j][e] = 0.f;

        #pragma unroll
        for (int kb8 = 0; kb8 < 8; kb8++) {
            uint32_t goff = (uint32_t)(((kb8 * 2 + l16) ^ qx) << 4);
            uint32_t qh[4], ql[4];
            ldsm4(qh, qbaseH + goff);
            ldsm4(ql, qbaseL + goff);
            #pragma unroll
            for (int ntp = 0; ntp < 4; ntp++) {
                int kr = ntp * 16 + l15;
                uint32_t koff = swz(kr, kb8 * 2 + l16, 0);
                uint32_t kh[4], kl[4];
                ldsm4(kh, sb + SM_KHI + koff);
                ldsm4(kl, sb + SM_KLO + koff);
                mma16816(sc[2 * ntp],     qh, kh[0], kh[2]);
                mma16816(sc[2 * ntp],     ql, kh[0], kh[2]);
                mma16816(sc[2 * ntp],     qh, kl[0], kl[2]);
                mma16816(sc[2 * ntp + 1], qh, kh[1], kh[3]);
                mma16816(sc[2 * ntp + 1], ql, kh[1], kh[3]);
                mma16816(sc[2 * ntp + 1], qh, kl[1], kl[3]);
            }
        }

        // ---- causal mask (only near the diagonal) ----
        if (c * 64 + 63 > grow0) {
            #pragma unroll
            for (int j = 0; j < 8; j++) {
                int gcol = c * 64 + j * 8 + tg * 2;
                if (gcol     > grow0)     sc[j][0] = -INFINITY;
                if (gcol + 1 > grow0)     sc[j][1] = -INFINITY;
                if (gcol     > grow0 + 8) sc[j][2] = -INFINITY;
                if (gcol + 1 > grow0 + 8) sc[j][3] = -INFINITY;
            }
        }

        // ---- online softmax (warp-local; rows grp and grp+8) ----
        float mx0 = -INFINITY, mx1 = -INFINITY;
        #pragma unroll
        for (int j = 0; j < 8; j++) {
            mx0 = fmaxf(mx0, fmaxf(sc[j][0], sc[j][1]));
            mx1 = fmaxf(mx1, fmaxf(sc[j][2], sc[j][3]));
        }
        mx0 = fmaxf(mx0, __shfl_xor_sync(0xffffffffu, mx0, 1));
        mx0 = fmaxf(mx0, __shfl_xor_sync(0xffffffffu, mx0, 2));
        mx1 = fmaxf(mx1, __shfl_xor_sync(0xffffffffu, mx1, 1));
        mx1 = fmaxf(mx1, __shfl_xor_sync(0xffffffffu, mx1, 2));
        float mn0 = fmaxf(mA, mx0), mn1 = fmaxf(mB, mx1);
        float al0 = __expf(mA - mn0), al1 = __expf(mB - mn1);
        mA = mn0; mB = mn1;
        float s0 = 0.f, s1 = 0.f;
        #pragma unroll
        for (int j = 0; j < 8; j++) {
            sc[j][0] = __expf(sc[j][0] - mn0); s0 += sc[j][0];
            sc[j][1] = __expf(sc[j][1] - mn0); s0 += sc[j][1];
            sc[j][2] = __expf(sc[j][2] - mn1); s1 += sc[j][2];
            sc[j][3] = __expf(sc[j][3] - mn1); s1 += sc[j][3];
        }
        s0 += __shfl_xor_sync(0xffffffffu, s0, 1);
        s0 += __shfl_xor_sync(0xffffffffu, s0, 2);
        s1 += __shfl_xor_sync(0xffffffffu, s1, 1);
        s1 += __shfl_xor_sync(0xffffffffu, s1, 2);
        lA = lA * al0 + s0;
        lB = lB * al1 + s1;
        #pragma unroll
        for (int j = 0; j < 16; j++) {
            o_[j][0] *= al0; o_[j][1] *= al0;
            o_[j][2] *= al1; o_[j][3] *= al1;
        }

        // ---- O += P V  (P from C-frags, split; V via ldmatrix.trans) ----
        #pragma unroll
        for (int s = 0; s < 4; s++) {
            uint32_t ph[4], pl[4];
            split2(sc[2 * s][0],     sc[2 * s][1],     ph[0], pl[0]);
            split2(sc[2 * s][2],     sc[2 * s][3],     ph[1], pl[1]);
            split2(sc[2 * s + 1][0], sc[2 * s + 1][1], ph[2], pl[2]);
            split2(sc[2 * s + 1][2], sc[2 * s + 1][3], ph[3], pl[3]);
            int vr = s * 16 + l15;
            #pragma unroll
            for (int dp = 0; dp < 8; dp++) {
                uint32_t voff = swz(vr, dp * 2 + l16, 0);
                uint32_t vh[4], vl[4];
                ldsm4t(vh, sb + SM_VHI + voff);
                ldsm4t(vl, sb + SM_VLO + voff);
                mma16816(o_[2 * dp],     ph, vh[0], vh[1]);
                mma16816(o_[2 * dp],     pl, vh[0], vh[1]);
                mma16816(o_[2 * dp],     ph, vl[0], vl[1]);
                mma16816(o_[2 * dp + 1], ph, vh[2], vh[3]);
                mma16816(o_[2 * dp + 1], pl, vh[2], vh[3]);
                mma16816(o_[2 * dp + 1], ph, vl[2], vl[3]);
            }
        }
    }

    // ---- epilogue: normalize + store ----
    float inv0 = 1.0f / lA, inv1 = 1.0f / lB;
    float* r0 = ob + (size_t)(w * 16 + grp) * 128 + tg * 2;
    float* r1 = ob + (size_t)(w * 16 + grp + 8) * 128 + tg * 2;
    #pragma unroll
    for (int j = 0; j < 16; j++) {
        *(float2*)(r0 + j * 8) = make_float2(o_[j][0] * inv0, o_[j][1] * inv0);
        *(float2*)(r1 + j * 8) = make_float2(o_[j][2] * inv1, o_[j][3] * inv1);
    }
}

extern "C" void kernel_launch(void* const* d_in, const int* in_sizes, int n_in,
                              void* d_out, int out_size) {
    const float* q = (const float*)d_in[0];
    const float* k = (const float*)d_in[1];
    const float* v = (const float*)d_in[2];
    // d_in[3]: causal tril mask — semantics implemented directly.
    float* out = (float*)d_out;
    const int S = 2048, D = 128;
    const int BH = in_sizes[0] / (S * D);   // 32
    cudaFuncSetAttribute(fa_mma_kernel,
                         cudaFuncAttributeMaxDynamicSharedMemorySize, SM_TOTAL);
    dim3 grid(S / BM, BH);
    fa_mma_kernel<<<grid, NTH, SM_TOTAL>>>(q, k, v, out);
}

// round 7
// speedup vs baseline: 3.3577x; 1.0619x over previous
#include <cuda_runtime.h>
#include <math.h>
#include <stdint.h>

#define NTH 128
#define BM 64
#define BN 64

// smem byte offsets (per CTA, 96KB total -> 2 CTAs/SM)
#define SM_QHI 0
#define SM_QLO 16384
#define SM_KHI 32768
#define SM_KLO 49152
#define SM_VHI 65536
#define SM_VLO 81920
#define SM_TOTAL 98304

static __device__ __forceinline__ uint32_t s2u(const void* p) {
    return (uint32_t)__cvta_generic_to_shared((void*)p);
}

// split fp32 pair -> bf16x2 hi + bf16x2 lo (rn split; lo compensates hi)
static __device__ __forceinline__ void split2(float x, float y,
                                              uint32_t& hi, uint32_t& lo) {
    uint32_t h2;
    asm("cvt.rn.bf16x2.f32 %0, %1, %2;" : "=r"(h2) : "f"(y), "f"(x));
    float hx = __uint_as_float(h2 << 16);
    float hy = __uint_as_float(h2 & 0xffff0000u);
    float lx = x - hx, ly = y - hy;
    uint32_t l2;
    asm("cvt.rn.bf16x2.f32 %0, %1, %2;" : "=r"(l2) : "f"(ly), "f"(lx));
    hi = h2; lo = l2;
}

static __device__ __forceinline__ void ldsm4(uint32_t* r, uint32_t a) {
    asm volatile("ldmatrix.sync.aligned.m8n8.x4.shared.b16 {%0,%1,%2,%3}, [%4];"
                 : "=r"(r[0]), "=r"(r[1]), "=r"(r[2]), "=r"(r[3]) : "r"(a));
}
static __device__ __forceinline__ void ldsm4t(uint32_t* r, uint32_t a) {
    asm volatile("ldmatrix.sync.aligned.m8n8.x4.trans.shared.b16 {%0,%1,%2,%3}, [%4];"
                 : "=r"(r[0]), "=r"(r[1]), "=r"(r[2]), "=r"(r[3]) : "r"(a));
}

static __device__ __forceinline__ void mma16816(float* c, const uint32_t* a,
                                                uint32_t b0, uint32_t b1) {
    asm volatile(
        "mma.sync.aligned.m16n8k16.row.col.f32.bf16.bf16.f32 "
        "{%0,%1,%2,%3}, {%4,%5,%6,%7}, {%8,%9}, {%0,%1,%2,%3};"
        : "+f"(c[0]), "+f"(c[1]), "+f"(c[2]), "+f"(c[3])
        : "r"(a[0]), "r"(a[1]), "r"(a[2]), "r"(a[3]), "r"(b0), "r"(b1));
}

// swizzled byte offset for (row, 16B-granule g, 8B half hb) in a 256B-row tile
static __device__ __forceinline__ uint32_t swz(int row, int g, int hb) {
    return (uint32_t)row * 256u + (uint32_t)((g ^ (row & 7)) << 4) + (uint32_t)hb * 8u;
}

__global__ __launch_bounds__(NTH, 2)
void fa_mma_kernel(const float* __restrict__ gq, const float* __restrict__ gk,
                   const float* __restrict__ gv, float* __restrict__ go)
{
    extern __shared__ char smem[];
    const uint32_t sb = s2u(smem);
    const int tid = threadIdx.x;
    const int w   = tid >> 5, ln = tid & 31;
    const int grp = ln >> 2, tg = ln & 3;
    const int l15 = ln & 15, l16 = ln >> 4;
    const int qt  = (int)gridDim.x - 1 - (int)blockIdx.x;   // heavy CTAs first
    const int bh  = blockIdx.y;
    const int S   = 2048;

    const float* qb  = gq + ((size_t)bh * S + (size_t)qt * BM) * 128;
    const float* kbh = gk + (size_t)bh * S * 128;
    const float* vbh = gv + (size_t)bh * S * 128;
    float*       ob  = go + ((size_t)bh * S + (size_t)qt * BM) * 128;

    // ---- Q: load fp32, split to bf16 hi/lo in smem (once) ----
    #pragma unroll
    for (int i = 0; i < 16; i++) {
        int f = tid + i * NTH;               // float4 idx; row=f>>5, c4=f&31
        int r = f >> 5, c4 = f & 31;
        float4 qq = ((const float4*)qb)[f];
        uint32_t h0, l0, h1, l1;
        split2(qq.x, qq.y, h0, l0);
        split2(qq.z, qq.w, h1, l1);
        uint32_t off = swz(r, c4 >> 1, c4 & 1);
        *(uint2*)(smem + SM_QHI + off) = make_uint2(h0, h1);
        *(uint2*)(smem + SM_QLO + off) = make_uint2(l0, l1);
    }

    float o_[16][4];
    #pragma unroll
    for (int j = 0; j < 16; j++)
        #pragma unroll
        for (int e = 0; e < 4; e++) o_[j][e] = 0.f;
    float mA = -INFINITY, mB = -INFINITY, lA = 0.f, lB = 0.f;

    const int qr = w * 16 + l15;             // ldmatrix source row for Q frags
    const uint32_t qbaseH = sb + SM_QHI + qr * 256;
    const uint32_t qbaseL = sb + SM_QLO + qr * 256;
    const int qx = qr & 7;

    const int grow0 = qt * BM + w * 16 + grp;    // global q-row of c0/c1
    const int nch = qt + 1;

    for (int c = 0; c < nch; c++) {
        __syncthreads();                     // prior chunk's ldmatrix reads done
        const float* kb = kbh + (size_t)c * BN * 128;
        const float* vb = vbh + (size_t)c * BN * 128;
        #pragma unroll
        for (int i = 0; i < 16; i++) {
            int f = tid + i * NTH;           // rows 0..63
            int r = f >> 5, c4 = f & 31;
            uint32_t off = swz(r, c4 >> 1, c4 & 1);
            float4 kk = ((const float4*)kb)[f];
            uint32_t h0, l0, h1, l1;
            split2(kk.x, kk.y, h0, l0);
            split2(kk.z, kk.w, h1, l1);
            *(uint2*)(smem + SM_KHI + off) = make_uint2(h0, h1);
            *(uint2*)(smem + SM_KLO + off) = make_uint2(l0, l1);
            float4 vv = ((const float4*)vb)[f];
            split2(vv.x, vv.y, h0, l0);
            split2(vv.z, vv.w, h1, l1);
            *(uint2*)(smem + SM_VHI + off) = make_uint2(h0, h1);
            *(uint2*)(smem + SM_VLO + off) = make_uint2(l0, l1);
        }
        __syncthreads();

        // ---- S = Q K^T  (3-way split: hi*hi + lo*hi + hi*lo) ----
        float sc[8][4];
        #pragma unroll
        for (int j = 0; j < 8; j++)
            #pragma unroll
            for (int e = 0; e < 4; e++) sc[j][e] = 0.f;

        #pragma unroll
        for (int kb8 = 0; kb8 < 8; kb8++) {
            uint32_t goff = (uint32_t)(((kb8 * 2 + l16) ^ qx) << 4);
            uint32_t qh[4], ql[4];
            ldsm4(qh, qbaseH + goff);
            ldsm4(ql, qbaseL + goff);
            #pragma unroll
            for (int ntp = 0; ntp < 4; ntp++) {
                int kr = ntp * 16 + l15;
                uint32_t koff = swz(kr, kb8 * 2 + l16, 0);
                uint32_t kh[4], kl[4];
                ldsm4(kh, sb + SM_KHI + koff);
                ldsm4(kl, sb + SM_KLO + koff);
                mma16816(sc[2 * ntp],     qh, kh[0], kh[2]);
                mma16816(sc[2 * ntp],     ql, kh[0], kh[2]);
                mma16816(sc[2 * ntp],     qh, kl[0], kl[2]);
                mma16816(sc[2 * ntp + 1], qh, kh[1], kh[3]);
                mma16816(sc[2 * ntp + 1], ql, kh[1], kh[3]);
                mma16816(sc[2 * ntp + 1], qh, kl[1], kl[3]);
            }
        }

        // ---- causal mask (only near the diagonal) ----
        if (c * BN + 63 > grow0) {
            #pragma unroll
            for (int j = 0; j < 8; j++) {
                int gcol = c * BN + j * 8 + tg * 2;
                if (gcol     > grow0)     sc[j][0] = -INFINITY;
                if (gcol + 1 > grow0)     sc[j][1] = -INFINITY;
                if (gcol     > grow0 + 8) sc[j][2] = -INFINITY;
                if (gcol + 1 > grow0 + 8) sc[j][3] = -INFINITY;
            }
        }

        // ---- online softmax (warp-local; rows grp and grp+8) ----
        float mx0 = -INFINITY, mx1 = -INFINITY;
        #pragma unroll
        for (int j = 0; j < 8; j++) {
            mx0 = fmaxf(mx0, fmaxf(sc[j][0], sc[j][1]));
            mx1 = fmaxf(mx1, fmaxf(sc[j][2], sc[j][3]));
        }
        mx0 = fmaxf(mx0, __shfl_xor_sync(0xffffffffu, mx0, 1));
        mx0 = fmaxf(mx0, __shfl_xor_sync(0xffffffffu, mx0, 2));
        mx1 = fmaxf(mx1, __shfl_xor_sync(0xffffffffu, mx1, 1));
        mx1 = fmaxf(mx1, __shfl_xor_sync(0xffffffffu, mx1, 2));
        float mn0 = fmaxf(mA, mx0), mn1 = fmaxf(mB, mx1);
        float al0 = __expf(mA - mn0), al1 = __expf(mB - mn1);
        mA = mn0; mB = mn1;
        float s0 = 0.f, s1 = 0.f;
        #pragma unroll
        for (int j = 0; j < 8; j++) {
            sc[j][0] = __expf(sc[j][0] - mn0); s0 += sc[j][0];
            sc[j][1] = __expf(sc[j][1] - mn0); s0 += sc[j][1];
            sc[j][2] = __expf(sc[j][2] - mn1); s1 += sc[j][2];
            sc[j][3] = __expf(sc[j][3] - mn1); s1 += sc[j][3];
        }
        s0 += __shfl_xor_sync(0xffffffffu, s0, 1);
        s0 += __shfl_xor_sync(0xffffffffu, s0, 2);
        s1 += __shfl_xor_sync(0xffffffffu, s1, 1);
        s1 += __shfl_xor_sync(0xffffffffu, s1, 2);
        lA = lA * al0 + s0;
        lB = lB * al1 + s1;
        #pragma unroll
        for (int j = 0; j < 16; j++) {
            o_[j][0] *= al0; o_[j][1] *= al0;
            o_[j][2] *= al1; o_[j][3] *= al1;
        }

        // ---- O += P V  (P from C-frags, split; V via ldmatrix.trans) ----
        #pragma unroll
        for (int s = 0; s < 4; s++) {
            uint32_t ph[4], pl[4];
            split2(sc[2 * s][0],     sc[2 * s][1],     ph[0], pl[0]);
            split2(sc[2 * s][2],     sc[2 * s][3],     ph[1], pl[1]);
            split2(sc[2 * s + 1][0], sc[2 * s + 1][1], ph[2], pl[2]);
            split2(sc[2 * s + 1][2], sc[2 * s + 1][3], ph[3], pl[3]);
            int vr = s * 16 + l15;
            #pragma unroll
            for (int dp = 0; dp < 8; dp++) {
                uint32_t voff = swz(vr, dp * 2 + l16, 0);
                uint32_t vh[4], vl[4];
                ldsm4t(vh, sb + SM_VHI + voff);
                ldsm4t(vl, sb + SM_VLO + voff);
                mma16816(o_[2 * dp],     ph, vh[0], vh[1]);
                mma16816(o_[2 * dp],     pl, vh[0], vh[1]);
                mma16816(o_[2 * dp],     ph, vl[0], vl[1]);
                mma16816(o_[2 * dp + 1], ph, vh[2], vh[3]);
                mma16816(o_[2 * dp + 1], pl, vh[2], vh[3]);
                mma16816(o_[2 * dp + 1], ph, vl[2], vl[3]);
            }
        }
    }

    // ---- epilogue: normalize + store ----
    float inv0 = 1.0f / lA, inv1 = 1.0f / lB;
    float* r0 = ob + (size_t)(w * 16 + grp) * 128 + tg * 2;
    float* r1 = ob + (size_t)(w * 16 + grp + 8) * 128 + tg * 2;
    #pragma unroll
    for (int j = 0; j < 16; j++) {
        *(float2*)(r0 + j * 8) = make_float2(o_[j][0] * inv0, o_[j][1] * inv0);
        *(float2*)(r1 + j * 8) = make_float2(o_[j][2] * inv1, o_[j][3] * inv1);
    }
}

extern "C" void kernel_launch(void* const* d_in, const int* in_sizes, int n_in,
                              void* d_out, int out_size) {
    const float* q = (const float*)d_in[0];
    const float* k = (const float*)d_in[1];
    const float* v = (const float*)d_in[2];
    // d_in[3]: causal tril mask — semantics implemented directly.
    float* out = (float*)d_out;
    const int S = 2048, D = 128;
    const int BH = in_sizes[0] / (S * D);   // 32
    cudaFuncSetAttribute(fa_mma_kernel,
                         cudaFuncAttributeMaxDynamicSharedMemorySize, SM_TOTAL);
    dim3 grid(S / BM, BH);
    fa_mma_kernel<<<grid, NTH, SM_TOTAL>>>(q, k, v, out);
}

// round 8
// speedup vs baseline: 3.6667x; 1.0920x over previous
#include <cuda_runtime.h>
#include <math.h>
#include <stdint.h>

#define NTH 128
#define BM 64
#define BN 64
#define BH 32
#define SEQ 2048

// smem byte offsets (per CTA, 96KB total -> 2 CTAs/SM)
#define SM_QHI 0
#define SM_QLO 16384
#define SM_KHI 32768
#define SM_KLO 49152
#define SM_VHI 65536
#define SM_VLO 81920
#define SM_TOTAL 98304

#define NF4 (BH * SEQ * 128 / 4)     // float4 count per tensor = 2,097,152

// pre-split bf16 hi/lo planes for K and V (one uint2 = 2x bf16x2 = 4 elems)
__device__ __align__(16) uint2 gKhi[NF4];
__device__ __align__(16) uint2 gKlo[NF4];
__device__ __align__(16) uint2 gVhi[NF4];
__device__ __align__(16) uint2 gVlo[NF4];

static __device__ __forceinline__ uint32_t s2u(const void* p) {
    return (uint32_t)__cvta_generic_to_shared((void*)p);
}

// split fp32 pair -> bf16x2 hi + bf16x2 lo (rn split; lo compensates hi)
static __device__ __forceinline__ void split2(float x, float y,
                                              uint32_t& hi, uint32_t& lo) {
    uint32_t h2;
    asm("cvt.rn.bf16x2.f32 %0, %1, %2;" : "=r"(h2) : "f"(y), "f"(x));
    float hx = __uint_as_float(h2 << 16);
    float hy = __uint_as_float(h2 & 0xffff0000u);
    float lx = x - hx, ly = y - hy;
    uint32_t l2;
    asm("cvt.rn.bf16x2.f32 %0, %1, %2;" : "=r"(l2) : "f"(ly), "f"(lx));
    hi = h2; lo = l2;
}

static __device__ __forceinline__ void ldsm4(uint32_t* r, uint32_t a) {
    asm volatile("ldmatrix.sync.aligned.m8n8.x4.shared.b16 {%0,%1,%2,%3}, [%4];"
                 : "=r"(r[0]), "=r"(r[1]), "=r"(r[2]), "=r"(r[3]) : "r"(a));
}
static __device__ __forceinline__ void ldsm4t(uint32_t* r, uint32_t a) {
    asm volatile("ldmatrix.sync.aligned.m8n8.x4.trans.shared.b16 {%0,%1,%2,%3}, [%4];"
                 : "=r"(r[0]), "=r"(r[1]), "=r"(r[2]), "=r"(r[3]) : "r"(a));
}

static __device__ __forceinline__ void mma16816(float* c, const uint32_t* a,
                                                uint32_t b0, uint32_t b1) {
    asm volatile(
        "mma.sync.aligned.m16n8k16.row.col.f32.bf16.bf16.f32 "
        "{%0,%1,%2,%3}, {%4,%5,%6,%7}, {%8,%9}, {%0,%1,%2,%3};"
        : "+f"(c[0]), "+f"(c[1]), "+f"(c[2]), "+f"(c[3])
        : "r"(a[0]), "r"(a[1]), "r"(a[2]), "r"(a[3]), "r"(b0), "r"(b1));
}

static __device__ __forceinline__ void cp16(uint32_t smem_dst, const void* gsrc) {
    asm volatile("cp.async.cg.shared.global [%0], [%1], 16;"
                 :: "r"(smem_dst), "l"(gsrc) : "memory");
}
static __device__ __forceinline__ void cp_commit() {
    asm volatile("cp.async.commit_group;" ::: "memory");
}
static __device__ __forceinline__ void cp_wait0() {
    asm volatile("cp.async.wait_group 0;" ::: "memory");
}

// swizzled byte offset for (row, 16B-granule g, 8B half hb) in a 256B-row tile
static __device__ __forceinline__ uint32_t swz(int row, int g, int hb) {
    return (uint32_t)row * 256u + (uint32_t)((g ^ (row & 7)) << 4) + (uint32_t)hb * 8u;
}

// ---- pre-pass: split K and V fp32 -> bf16 hi/lo planes (once) ----
__global__ __launch_bounds__(256, 8)
void presplit_kernel(const float* __restrict__ gk, const float* __restrict__ gv)
{
    int i = blockIdx.x * 256 + threadIdx.x;      // float4 index
    const float* src = blockIdx.y ? gv : gk;
    uint2* dhi = blockIdx.y ? gVhi : gKhi;
    uint2* dlo = blockIdx.y ? gVlo : gKlo;
    float4 x = ((const float4*)src)[i];
    uint32_t h0, l0, h1, l1;
    split2(x.x, x.y, h0, l0);
    split2(x.z, x.w, h1, l1);
    dhi[i] = make_uint2(h0, h1);
    dlo[i] = make_uint2(l0, l1);
}

__global__ __launch_bounds__(NTH, 2)
void fa_mma_kernel(const float* __restrict__ gq, float* __restrict__ go)
{
    extern __shared__ char smem[];
    const uint32_t sb = s2u(smem);
    const int tid = threadIdx.x;
    const int w   = tid >> 5, ln = tid & 31;
    const int grp = ln >> 2, tg = ln & 3;
    const int l15 = ln & 15, l16 = ln >> 4;
    const int qt  = (int)gridDim.x - 1 - (int)blockIdx.x;   // heavy CTAs first
    const int bh  = blockIdx.y;

    const float* qb = gq + ((size_t)bh * SEQ + (size_t)qt * BM) * 128;
    float*       ob = go + ((size_t)bh * SEQ + (size_t)qt * BM) * 128;
    const char* kbhi = (const char*)gKhi + (size_t)bh * SEQ * 256;
    const char* kblo = (const char*)gKlo + (size_t)bh * SEQ * 256;
    const char* vbhi = (const char*)gVhi + (size_t)bh * SEQ * 256;
    const char* vblo = (const char*)gVlo + (size_t)bh * SEQ * 256;

    // ---- Q: load fp32, split to bf16 hi/lo in smem (once per CTA) ----
    #pragma unroll
    for (int i = 0; i < 16; i++) {
        int f = tid + i * NTH;               // float4 idx; row=f>>5, c4=f&31
        int r = f >> 5, c4 = f & 31;
        float4 qq = ((const float4*)qb)[f];
        uint32_t h0, l0, h1, l1;
        split2(qq.x, qq.y, h0, l0);
        split2(qq.z, qq.w, h1, l1);
        uint32_t off = swz(r, c4 >> 1, c4 & 1);
        *(uint2*)(smem + SM_QHI + off) = make_uint2(h0, h1);
        *(uint2*)(smem + SM_QLO + off) = make_uint2(l0, l1);
    }

    float o_[16][4];
    #pragma unroll
    for (int j = 0; j < 16; j++)
        #pragma unroll
        for (int e = 0; e < 4; e++) o_[j][e] = 0.f;
    float mA = -INFINITY, mB = -INFINITY, lA = 0.f, lB = 0.f;

    const int qr = w * 16 + l15;             // ldmatrix source row for Q frags
    const uint32_t qbaseH = sb + SM_QHI + qr * 256;
    const uint32_t qbaseL = sb + SM_QLO + qr * 256;
    const int qx = qr & 7;

    const int grow0 = qt * BM + w * 16 + grp;    // global q-row of c0/c1
    const int nch = qt + 1;

    for (int c = 0; c < nch; c++) {
        __syncthreads();                     // prior chunk's ldmatrix reads done

        // ---- fill K/V bf16 tiles via cp.async (pre-split in gmem) ----
        size_t tbase = (size_t)c * BN * 256; // tile byte offset within bh plane
        #pragma unroll
        for (int i = 0; i < 8; i++) {
            int f = tid + i * NTH;           // granule 0..1023
            int r = f >> 4, g = f & 15;
            uint32_t d = (uint32_t)r * 256u + (uint32_t)((g ^ (r & 7)) << 4);
            size_t s = tbase + (size_t)f * 16u;
            cp16(sb + SM_KHI + d, kbhi + s);
            cp16(sb + SM_KLO + d, kblo + s);
            cp16(sb + SM_VHI + d, vbhi + s);
            cp16(sb + SM_VLO + d, vblo + s);
        }
        cp_commit();
        cp_wait0();
        __syncthreads();

        // ---- S = Q K^T  (3-way split: hi*hi + lo*hi + hi*lo) ----
        float sc[8][4];
        #pragma unroll
        for (int j = 0; j < 8; j++)
            #pragma unroll
            for (int e = 0; e < 4; e++) sc[j][e] = 0.f;

        #pragma unroll
        for (int kb8 = 0; kb8 < 8; kb8++) {
            uint32_t goff = (uint32_t)(((kb8 * 2 + l16) ^ qx) << 4);
            uint32_t qh[4], ql[4];
            ldsm4(qh, qbaseH + goff);
            ldsm4(ql, qbaseL + goff);
            #pragma unroll
            for (int ntp = 0; ntp < 4; ntp++) {
                int kr = ntp * 16 + l15;
                uint32_t koff = swz(kr, kb8 * 2 + l16, 0);
                uint32_t kh[4], kl[4];
                ldsm4(kh, sb + SM_KHI + koff);
                ldsm4(kl, sb + SM_KLO + koff);
                mma16816(sc[2 * ntp],     qh, kh[0], kh[2]);
                mma16816(sc[2 * ntp],     ql, kh[0], kh[2]);
                mma16816(sc[2 * ntp],     qh, kl[0], kl[2]);
                mma16816(sc[2 * ntp + 1], qh, kh[1], kh[3]);
                mma16816(sc[2 * ntp + 1], ql, kh[1], kh[3]);
                mma16816(sc[2 * ntp + 1], qh, kl[1], kl[3]);
            }
        }

        // ---- causal mask (only near the diagonal) ----
        if (c * BN + 63 > grow0) {
            #pragma unroll
            for (int j = 0; j < 8; j++) {
                int gcol = c * BN + j * 8 + tg * 2;
                if (gcol     > grow0)     sc[j][0] = -INFINITY;
                if (gcol + 1 > grow0)     sc[j][1] = -INFINITY;
                if (gcol     > grow0 + 8) sc[j][2] = -INFINITY;
                if (gcol + 1 > grow0 + 8) sc[j][3] = -INFINITY;
            }
        }

        // ---- online softmax (warp-local; rows grp and grp+8) ----
        float mx0 = -INFINITY, mx1 = -INFINITY;
        #pragma unroll
        for (int j = 0; j < 8; j++) {
            mx0 = fmaxf(mx0, fmaxf(sc[j][0], sc[j][1]));
            mx1 = fmaxf(mx1, fmaxf(sc[j][2], sc[j][3]));
        }
        mx0 = fmaxf(mx0, __shfl_xor_sync(0xffffffffu, mx0, 1));
        mx0 = fmaxf(mx0, __shfl_xor_sync(0xffffffffu, mx0, 2));
        mx1 = fmaxf(mx1, __shfl_xor_sync(0xffffffffu, mx1, 1));
        mx1 = fmaxf(mx1, __shfl_xor_sync(0xffffffffu, mx1, 2));
        float mn0 = fmaxf(mA, mx0), mn1 = fmaxf(mB, mx1);
        float al0 = __expf(mA - mn0), al1 = __expf(mB - mn1);
        mA = mn0; mB = mn1;
        float s0 = 0.f, s1 = 0.f;
        #pragma unroll
        for (int j = 0; j < 8; j++) {
            sc[j][0] = __expf(sc[j][0] - mn0); s0 += sc[j][0];
            sc[j][1] = __expf(sc[j][1] - mn0); s0 += sc[j][1];
            sc[j][2] = __expf(sc[j][2] - mn1); s1 += sc[j][2];
            sc[j][3] = __expf(sc[j][3] - mn1); s1 += sc[j][3];
        }
        s0 += __shfl_xor_sync(0xffffffffu, s0, 1);
        s0 += __shfl_xor_sync(0xffffffffu, s0, 2);
        s1 += __shfl_xor_sync(0xffffffffu, s1, 1);
        s1 += __shfl_xor_sync(0xffffffffu, s1, 2);
        lA = lA * al0 + s0;
        lB = lB * al1 + s1;
        #pragma unroll
        for (int j = 0; j < 16; j++) {
            o_[j][0] *= al0; o_[j][1] *= al0;
            o_[j][2] *= al1; o_[j][3] *= al1;
        }

        // ---- O += P V  (P from C-frags, split; V via ldmatrix.trans) ----
        #pragma unroll
        for (int s = 0; s < 4; s++) {
            uint32_t ph[4], pl[4];
            split2(sc[2 * s][0],     sc[2 * s][1],     ph[0], pl[0]);
            split2(sc[2 * s][2],     sc[2 * s][3],     ph[1], pl[1]);
            split2(sc[2 * s + 1][0], sc[2 * s + 1][1], ph[2], pl[2]);
            split2(sc[2 * s + 1][2], sc[2 * s + 1][3], ph[3], pl[3]);
            int vr = s * 16 + l15;
            #pragma unroll
            for (int dp = 0; dp < 8; dp++) {
                uint32_t voff = swz(vr, dp * 2 + l16, 0);
                uint32_t vh[4], vl[4];
                ldsm4t(vh, sb + SM_VHI + voff);
                ldsm4t(vl, sb + SM_VLO + voff);
                mma16816(o_[2 * dp],     ph, vh[0], vh[1]);
                mma16816(o_[2 * dp],     pl, vh[0], vh[1]);
                mma16816(o_[2 * dp],     ph, vl[0], vl[1]);
                mma16816(o_[2 * dp + 1], ph, vh[2], vh[3]);
                mma16816(o_[2 * dp + 1], pl, vh[2], vh[3]);
                mma16816(o_[2 * dp + 1], ph, vl[2], vl[3]);
            }
        }
    }

    // ---- epilogue: normalize + store ----
    float inv0 = 1.0f / lA, inv1 = 1.0f / lB;
    float* r0 = ob + (size_t)(w * 16 + grp) * 128 + tg * 2;
    float* r1 = ob + (size_t)(w * 16 + grp + 8) * 128 + tg * 2;
    #pragma unroll
    for (int j = 0; j < 16; j++) {
        *(float2*)(r0 + j * 8) = make_float2(o_[j][0] * inv0, o_[j][1] * inv0);
        *(float2*)(r1 + j * 8) = make_float2(o_[j][2] * inv1, o_[j][3] * inv1);
    }
}

extern "C" void kernel_launch(void* const* d_in, const int* in_sizes, int n_in,
                              void* d_out, int out_size) {
    const float* q = (const float*)d_in[0];
    const float* k = (const float*)d_in[1];
    const float* v = (const float*)d_in[2];
    // d_in[3]: causal tril mask — semantics implemented directly.
    float* out = (float*)d_out;

    dim3 pgrid(NF4 / 256, 2);
    presplit_kernel<<<pgrid, 256>>>(k, v);

    cudaFuncSetAttribute(fa_mma_kernel,
                         cudaFuncAttributeMaxDynamicSharedMemorySize, SM_TOTAL);
    dim3 grid(SEQ / BM, BH);
    fa_mma_kernel<<<grid, NTH, SM_TOTAL>>>(q, out);
}